// round 2
// baseline (speedup 1.0000x reference)
#include <cuda_runtime.h>
#include <cuda_bf16.h>
#include <cstdint>

#define N_NODES_MAX 100000
#define DSIGMA_DT (-0.0001f)
#define PHI_THRESH 0.3f
#define EPS 1e-8f

// Scratch accumulator: {num.x, num.y, num.z, cnt} per node.
__device__ float4 g_acc[N_NODES_MAX];
// 1 if edge_index is int64, 0 if int32.
__device__ int g_idx_is64;

__global__ void detect_and_zero_kernel(const unsigned int* __restrict__ ei_words,
                                       int n_nodes) {
    int i = blockIdx.x * blockDim.x + threadIdx.x;
    if (i < n_nodes) {
        g_acc[i] = make_float4(0.f, 0.f, 0.f, 0.f);
    }
    if (blockIdx.x == 0 && threadIdx.x == 0) {
        // If int64 little-endian with values < 2^31, odd words are all zero.
        unsigned int acc = 0;
        #pragma unroll
        for (int k = 0; k < 64; k++) {
            acc |= ei_words[2 * k + 1];
        }
        g_idx_is64 = (acc == 0) ? 1 : 0;
    }
}

__global__ void edge_scatter_kernel(const float* __restrict__ x,
                                    const float* __restrict__ pos,
                                    const void* __restrict__ edge_index,
                                    int n_edges) {
    int e = blockIdx.x * blockDim.x + threadIdx.x;
    if (e >= n_edges) return;

    int src, dst;
    if (g_idx_is64) {
        const long long* ei = (const long long*)edge_index;
        src = (int)ei[e];
        dst = (int)ei[n_edges + e];
    } else {
        const int* ei = (const int*)edge_index;
        src = ei[e];
        dst = ei[n_edges + e];
    }

    // T = x[:,3]
    float Ts = __ldg(&x[src * 9 + 3]);
    float Td = __ldg(&x[dst * 9 + 3]);
    float dT = Ts - Td;

    float px = __ldg(&pos[src * 3 + 0]) - __ldg(&pos[dst * 3 + 0]);
    float py = __ldg(&pos[src * 3 + 1]) - __ldg(&pos[dst * 3 + 1]);
    float pz = __ldg(&pos[src * 3 + 2]) - __ldg(&pos[dst * 3 + 2]);

    float dist2 = px * px + py * py + pz * pz + EPS;
    float w = dT / dist2;

    float cx = w * px;
    float cy = w * py;
    float cz = w * pz;

    // Single 128-bit reduction per edge: {num.xyz, cnt}
    float4* addr = &g_acc[dst];
    asm volatile("red.global.add.v4.f32 [%0], {%1, %2, %3, %4};"
                 :: "l"(addr), "f"(cx), "f"(cy), "f"(cz), "f"(1.0f)
                 : "memory");
}

__global__ void finalize_kernel(const float* __restrict__ x,
                                float* __restrict__ out,
                                int n_nodes) {
    int i = blockIdx.x * blockDim.x + threadIdx.x;
    if (i >= n_nodes) return;

    float4 a = g_acc[i];
    float cnt = fmaxf(a.w, 1.0f);
    float inv = 1.0f / cnt;

    float phi = x[i * 9 + 8];
    float mask = (fabsf(phi) < PHI_THRESH) ? 1.0f : 0.0f;
    float s = DSIGMA_DT * inv * mask;

    out[i * 3 + 0] = s * a.x;
    out[i * 3 + 1] = s * a.y;
    out[i * 3 + 2] = s * a.z;
}

extern "C" void kernel_launch(void* const* d_in, const int* in_sizes, int n_in,
                              void* d_out, int out_size) {
    const float* x = (const float*)d_in[0];    // [N, 9]
    const float* pos = (const float*)d_in[1];  // [N, 3]
    const void* edge_index = d_in[2];          // [2, E] int32 or int64

    int n_nodes = in_sizes[1] / 3;
    int n_edges = in_sizes[2] / 2;

    float* out = (float*)d_out;

    const int TPB = 256;
    detect_and_zero_kernel<<<(n_nodes + TPB - 1) / TPB, TPB>>>(
        (const unsigned int*)edge_index, n_nodes);
    edge_scatter_kernel<<<(n_edges + TPB - 1) / TPB, TPB>>>(x, pos, edge_index, n_edges);
    finalize_kernel<<<(n_nodes + TPB - 1) / TPB, TPB>>>(x, out, n_nodes);
}

// round 3
// speedup vs baseline: 1.7138x; 1.7138x over previous
#include <cuda_runtime.h>
#include <cuda_bf16.h>
#include <cstdint>

#define N_NODES_MAX 100000
#define DSIGMA_DT (-0.0001f)
#define PHI_THRESH 0.3f
#define EPS 1e-8f

// Scratch: packed {pos.x, pos.y, pos.z, T} per node, and {num.xyz, cnt} accumulator.
__device__ float4 g_packed[N_NODES_MAX];
__device__ float4 g_acc[N_NODES_MAX];
__device__ int g_idx_is64;

// One kernel: zero accumulators, pack pos+T into float4, detect index dtype.
__global__ void prep_kernel(const float* __restrict__ x,
                            const float* __restrict__ pos,
                            const unsigned int* __restrict__ ei_words,
                            int n_nodes) {
    int i = blockIdx.x * blockDim.x + threadIdx.x;
    if (i < n_nodes) {
        g_acc[i] = make_float4(0.f, 0.f, 0.f, 0.f);
        float4 p;
        p.x = pos[i * 3 + 0];
        p.y = pos[i * 3 + 1];
        p.z = pos[i * 3 + 2];
        p.w = x[i * 9 + 3];   // T
        g_packed[i] = p;
    }
    if (blockIdx.x == 0 && threadIdx.x == 0) {
        // int64 little-endian with values < 2^31 => odd 32-bit words all zero.
        unsigned int acc = 0;
        #pragma unroll
        for (int k = 0; k < 64; k++) {
            acc |= ei_words[2 * k + 1];
        }
        g_idx_is64 = (acc == 0) ? 1 : 0;
    }
}

__global__ void edge_scatter_kernel(const void* __restrict__ edge_index,
                                    int n_edges) {
    int e = blockIdx.x * blockDim.x + threadIdx.x;
    if (e >= n_edges) return;

    int src, dst;
    if (g_idx_is64) {
        const long long* ei = (const long long*)edge_index;
        src = (int)ei[e];
        dst = (int)ei[n_edges + e];
    } else {
        const int* ei = (const int*)edge_index;
        src = ei[e];
        dst = ei[n_edges + e];
    }

    // Two 128-bit gathers: {pos, T} for src and dst.
    float4 a = __ldg(&g_packed[src]);
    float4 b = __ldg(&g_packed[dst]);

    float dT = a.w - b.w;
    float px = a.x - b.x;
    float py = a.y - b.y;
    float pz = a.z - b.z;

    float dist2 = px * px + py * py + pz * pz + EPS;
    float w = dT / dist2;

    float cx = w * px;
    float cy = w * py;
    float cz = w * pz;

    // Single 128-bit reduction per edge: {num.xyz, cnt}
    float4* addr = &g_acc[dst];
    asm volatile("red.global.add.v4.f32 [%0], {%1, %2, %3, %4};"
                 :: "l"(addr), "f"(cx), "f"(cy), "f"(cz), "f"(1.0f)
                 : "memory");
}

__global__ void finalize_kernel(const float* __restrict__ x,
                                float* __restrict__ out,
                                int n_nodes) {
    int i = blockIdx.x * blockDim.x + threadIdx.x;
    if (i >= n_nodes) return;

    float4 a = g_acc[i];
    float cnt = fmaxf(a.w, 1.0f);
    float inv = 1.0f / cnt;

    float phi = x[i * 9 + 8];
    float mask = (fabsf(phi) < PHI_THRESH) ? 1.0f : 0.0f;
    float s = DSIGMA_DT * inv * mask;

    out[i * 3 + 0] = s * a.x;
    out[i * 3 + 1] = s * a.y;
    out[i * 3 + 2] = s * a.z;
}

extern "C" void kernel_launch(void* const* d_in, const int* in_sizes, int n_in,
                              void* d_out, int out_size) {
    const float* x = (const float*)d_in[0];    // [N, 9]
    const float* pos = (const float*)d_in[1];  // [N, 3]
    const void* edge_index = d_in[2];          // [2, E] int32 or int64

    int n_nodes = in_sizes[1] / 3;
    int n_edges = in_sizes[2] / 2;

    float* out = (float*)d_out;

    const int TPB = 256;
    prep_kernel<<<(n_nodes + TPB - 1) / TPB, TPB>>>(
        x, pos, (const unsigned int*)edge_index, n_nodes);
    edge_scatter_kernel<<<(n_edges + TPB - 1) / TPB, TPB>>>(edge_index, n_edges);
    finalize_kernel<<<(n_nodes + TPB - 1) / TPB, TPB>>>(x, out, n_nodes);
}